// round 15
// baseline (speedup 1.0000x reference)
#include <cuda_runtime.h>
#include <cuda_fp16.h>
#include <cuda_bf16.h>
#include <math.h>
#include <type_traits>

// ---------------------------------------------------------------------------
// GATLayers round 15 = R13 (best, 135.9us) + gemm1 re-tiled M128->M64:
// gemm1 was measured 17.3us, capped at ~25% occupancy purely by grid size
// (314 blocks / 148 SMs). M64 tile -> 626 blocks, 36.9KB smem, ~6 blocks/SM.
// R14's two changes (agg1 reg forcing, rps fusion) reverted (regressed).
// ---------------------------------------------------------------------------

constexpr int NN = 20000;
constexpr int EE = 640000;
constexpr int CB = (NN + 255) / 256;   // 79 scan blocks
constexpr int HB = EE / 256;           // 2500 hist/scatter blocks
constexpr int GB1 = (NN + 63) / 64;    // 313 gemm1 row-blocks (M=64)
constexpr int GB2 = (NN + 127) / 128;  // 157 gemm2 row-blocks (M=128)
constexpr int PAD2 = 136;              // gemm2 smem row stride (halves)
constexpr int PAD1 = 72;               // gemm1 smem row stride (halves)
constexpr int SM2_BYTES = (2 * 128 * PAD2 + 2 * 64 * PAD2) * 2;  // 104448
constexpr int SM1_BYTES = (2 * 64 * PAD1 + 2 * 64 * PAD1) * 2;   // 36864

// ------------------------------ scratch ------------------------------------
__device__ int    g_is64;
__device__ int    g_ready;
__device__ int    g_done;
__device__ int    g_tick;
__device__ int    g_deg[NN];
__device__ int    g_rowptr[NN + 1];
__device__ int    g_rank[EE];
__device__ int    g_col[EE];
__device__ int    g_bsum[CB];
__device__ __half g_h16[NN * 128];     // relu(bn(out1)) fp16
__device__ __half g_w1hi[128 * 64];    // W1^T hi fp16: [n][k]
__device__ __half g_w1lo[128 * 64];
__device__ __half g_w2hi[256 * 128];   // W2^T hi fp16: [n][k]
__device__ __half g_w2lo[256 * 128];
__device__ __half g_y1hi[NN * 128];    // aggregated layer1 hi
__device__ __half g_y1lo[NN * 128];
__device__ __half g_y2hi[NN * 256];    // aggregated layer2 hi
__device__ __half g_y2lo[NN * 256];
__device__ float  g_out1[NN * 128];
__device__ float  g_out2[NN * 256];
__device__ float  g_as1[NN * 2];
__device__ float  g_ad1[NN * 2];
__device__ float  g_as2[NN * 2];
__device__ float  g_ad2[NN * 2];
__device__ float  g_part[GB1 * 2 * 128 + 256];   // fits both layers' partials
__device__ float  g_scale[256];
__device__ float  g_shift[256];
__device__ float4 g_u1[64];
__device__ float4 g_u2[128];

// ------------------------------ helpers -------------------------------------
__device__ __forceinline__ void split16(float v, __half& h, __half& l) {
    h = __float2half_rn(v);
    l = __float2half_rn(v - __half2float(h));
}
__device__ __forceinline__ int edge_val(const void* ei, int idx, int is64) {
    if (is64) return (int)((const long long*)ei)[idx];
    return ((const int*)ei)[idx];
}
__device__ __forceinline__ void mma16816(
    float* c, const unsigned* a, const unsigned* b)
{
    asm volatile(
        "mma.sync.aligned.m16n8k16.row.col.f32.f16.f16.f32 "
        "{%0,%1,%2,%3}, {%4,%5,%6,%7}, {%8,%9}, {%0,%1,%2,%3};"
        : "+f"(c[0]), "+f"(c[1]), "+f"(c[2]), "+f"(c[3])
        : "r"(a[0]), "r"(a[1]), "r"(a[2]), "r"(a[3]), "r"(b[0]), "r"(b[1]));
}

// -------- prep: hist (per-block is64) + attvec + W2/W1 split-fp16 -----------
__global__ __launch_bounds__(256) void prep_kernel(
    const void* __restrict__ ei,
    const float* __restrict__ W1, const float* __restrict__ s1,
    const float* __restrict__ d1,
    const float* __restrict__ W2, const float* __restrict__ s2,
    const float* __restrict__ d2)
{
    const int bx = blockIdx.x;
    const int tid = threadIdx.x;
    if (bx < HB) {
        const int* ei32 = (const int*)ei;
        __shared__ int s_is64;
        if (tid < 32) {
            int a = ei32[2 * tid + 1];
            int b = ei32[2 * (tid + 32) + 1];
            unsigned m = __ballot_sync(0xffffffffu, (a | b) != 0);
            if (tid == 0) {
                s_is64 = (m == 0) ? 1 : 0;
                if (bx == 0) g_is64 = s_is64;
            }
        }
        __syncthreads();
        const int is64 = s_is64;
        int e = bx * 256 + tid;
        int dst = edge_val(ei, EE + e, is64);
        g_rank[e] = atomicAdd(&g_deg[dst], 1);
        return;
    }
    if (bx < HB + 24) {    // attention vectors
        const int lane = tid & 31;
        const int f = (bx - HB) * 8 + (tid >> 5);   // 0..191
        float4 u = make_float4(0.f, 0.f, 0.f, 0.f);
        if (f < 64) {
            #pragma unroll
            for (int c = lane; c < 64; c += 32) {
                float w0 = W1[f * 128 + c], w1 = W1[f * 128 + 64 + c];
                u.x += w0 * s1[c];      u.y += w1 * s1[64 + c];
                u.z += w0 * d1[c];      u.w += w1 * d1[64 + c];
            }
        } else {
            int f2 = f - 64;
            #pragma unroll
            for (int c = lane; c < 128; c += 32) {
                float w0 = W2[f2 * 256 + c], w1 = W2[f2 * 256 + 128 + c];
                u.x += w0 * s2[c];      u.y += w1 * s2[128 + c];
                u.z += w0 * d2[c];      u.w += w1 * d2[128 + c];
            }
        }
        #pragma unroll
        for (int o = 16; o; o >>= 1) {
            u.x += __shfl_xor_sync(0xffffffffu, u.x, o);
            u.y += __shfl_xor_sync(0xffffffffu, u.y, o);
            u.z += __shfl_xor_sync(0xffffffffu, u.z, o);
            u.w += __shfl_xor_sync(0xffffffffu, u.w, o);
        }
        if (lane == 0) {
            if (f < 64) g_u1[f] = u;
            else        g_u2[f - 64] = u;
        }
        return;
    }
    if (bx < HB + 56) {   // W2^T split: 32 blocks
        int t4 = (bx - HB - 24) * 256 + tid;
        int e = t4 * 4;
        int k = e >> 8;
        int n0 = e & 255;
        float4 w = *(const float4*)&W2[k * 256 + n0];
        __half h, l;
        split16(w.x, h, l); g_w2hi[(n0 + 0) * 128 + k] = h; g_w2lo[(n0 + 0) * 128 + k] = l;
        split16(w.y, h, l); g_w2hi[(n0 + 1) * 128 + k] = h; g_w2lo[(n0 + 1) * 128 + k] = l;
        split16(w.z, h, l); g_w2hi[(n0 + 2) * 128 + k] = h; g_w2lo[(n0 + 2) * 128 + k] = l;
        split16(w.w, h, l); g_w2hi[(n0 + 3) * 128 + k] = h; g_w2lo[(n0 + 3) * 128 + k] = l;
        return;
    }
    {   // W1^T split: 8 blocks
        int t4 = (bx - HB - 56) * 256 + tid;
        int e = t4 * 4;
        int k = e >> 7;
        int n0 = e & 127;
        float4 w = *(const float4*)&W1[k * 128 + n0];
        __half h, l;
        split16(w.x, h, l); g_w1hi[(n0 + 0) * 64 + k] = h; g_w1lo[(n0 + 0) * 64 + k] = l;
        split16(w.y, h, l); g_w1hi[(n0 + 1) * 64 + k] = h; g_w1lo[(n0 + 1) * 64 + k] = l;
        split16(w.z, h, l); g_w1hi[(n0 + 2) * 64 + k] = h; g_w1lo[(n0 + 2) * 64 + k] = l;
        split16(w.w, h, l); g_w1hi[(n0 + 3) * 64 + k] = h; g_w1lo[(n0 + 3) * 64 + k] = l;
    }
}

// ----------------- rowptr: scan + spin + deg reset for next replay ----------
__global__ __launch_bounds__(256) void rowptr_kernel() {
    __shared__ int s[256];
    const int t = threadIdx.x;
    const int bx = blockIdx.x;
    const int i = bx * 256 + t;
    int d = (i < NN) ? g_deg[i] : 0;
    if (i < NN) g_deg[i] = 0;
    s[t] = d;
    __syncthreads();
    for (int o = 1; o < 256; o <<= 1) {
        int u = (t >= o) ? s[t - o] : 0;
        __syncthreads();
        s[t] += u;
        __syncthreads();
    }
    const int incl = s[t];
    if (t == 255) {
        g_bsum[bx] = incl;
        __threadfence();
        atomicAdd(&g_ready, 1);
        while (atomicAdd(&g_ready, 0) < (int)gridDim.x) {}
    }
    __syncthreads();
    int pre = 0;
    for (int b = t; b < bx; b += 256) pre += g_bsum[b];
    #pragma unroll
    for (int o = 16; o; o >>= 1) pre += __shfl_xor_sync(0xffffffffu, pre, o);
    __shared__ int ws[8];
    if ((t & 31) == 0) ws[t >> 5] = pre;
    __syncthreads();
    if (t == 0) {
        int p = 0;
        #pragma unroll
        for (int w = 0; w < 8; w++) p += ws[w];
        s[0] = p;
    }
    __syncthreads();
    const int bpre = s[0];
    if (i < NN) g_rowptr[i] = bpre + incl - d;
    if (i == NN - 1) g_rowptr[NN] = bpre + incl;
    if (t == 0 && atomicAdd(&g_done, 1) == (int)gridDim.x - 1) {
        g_ready = 0;
        g_done = 0;
    }
}

// --------------------------- score GEMV body --------------------------------
template <int K, bool BN>
__device__ __forceinline__ void gemv_body(
    int node, const float* __restrict__ A, const float4* __restrict__ U,
    float* __restrict__ as_out, float* __restrict__ ad_out,
    __half* __restrict__ h16, int lane)
{
    float4 acc = make_float4(0.f, 0.f, 0.f, 0.f);
    #pragma unroll
    for (int f = lane; f < K; f += 32) {
        float v = A[(size_t)node * K + f];
        if (BN) {
            v = v * g_scale[f] + g_shift[f];
            v = v > 0.f ? v : 0.f;
            h16[(size_t)node * K + f] = __float2half_rn(v);
        }
        float4 u = U[f];
        acc.x += v * u.x; acc.y += v * u.y;
        acc.z += v * u.z; acc.w += v * u.w;
    }
    #pragma unroll
    for (int o = 16; o; o >>= 1) {
        acc.x += __shfl_xor_sync(0xffffffffu, acc.x, o);
        acc.y += __shfl_xor_sync(0xffffffffu, acc.y, o);
        acc.z += __shfl_xor_sync(0xffffffffu, acc.z, o);
        acc.w += __shfl_xor_sync(0xffffffffu, acc.w, o);
    }
    if (lane == 0) {
        as_out[node * 2 + 0] = acc.x;
        as_out[node * 2 + 1] = acc.y;
        ad_out[node * 2 + 0] = acc.z;
        ad_out[node * 2 + 1] = acc.w;
    }
}

__global__ __launch_bounds__(256) void scatter_gemv1_kernel(
    const void* __restrict__ ei, const float* __restrict__ x,
    const float4* __restrict__ U,
    float* __restrict__ as_out, float* __restrict__ ad_out)
{
    const int bx = blockIdx.x;
    if (bx < HB) {
        int e = bx * 256 + threadIdx.x;
        int is64 = g_is64;
        int src = edge_val(ei, e, is64);
        int dst = edge_val(ei, EE + e, is64);
        g_col[g_rowptr[dst] + g_rank[e]] = src;
        return;
    }
    const int node = (bx - HB) * 8 + (threadIdx.x >> 5);
    gemv_body<64, false>(node, x, U, as_out, ad_out, nullptr,
                         threadIdx.x & 31);
}

__global__ __launch_bounds__(256) void gemv2_kernel(
    const float* __restrict__ A, const float4* __restrict__ U,
    float* __restrict__ as_out, float* __restrict__ ad_out,
    __half* __restrict__ h16)
{
    const int node = blockIdx.x * 8 + (threadIdx.x >> 5);
    gemv_body<128, true>(node, A, U, as_out, ad_out, h16, threadIdx.x & 31);
}

// ------------------- segment softmax + weighted aggregate ------------------
// Batched-32 edges per warp. HALF_SRC: fp16 rows (layer 2) vs fp32 (layer 1).
template <int F, bool HALF_SRC>
__global__ __launch_bounds__(256) void agg_kernel(
    const void* __restrict__ srcv, const float* __restrict__ as,
    const float* __restrict__ ad,
    __half* __restrict__ yhi, __half* __restrict__ ylo)
{
    const int lane = threadIdx.x & 31;
    const int warp = threadIdx.x >> 5;
    const int node = blockIdx.x * 8 + warp;
    constexpr int V = F / 32;   // elems per lane: 2 or 4
    using RowT = typename std::conditional<
        HALF_SRC, typename std::conditional<V == 2, unsigned, uint2>::type,
                  typename std::conditional<V == 2, float2, float4>::type>::type;
    const int base = g_rowptr[node];
    const int deg = g_rowptr[node + 1] - base;
    const float2* as2 = (const float2*)as;
    const float2 adi = ((const float2*)ad)[node];

    float acc0[V], acc1[V];
    #pragma unroll
    for (int v = 0; v < V; v++) { acc0[v] = 0.f; acc1[v] = 0.f; }
    float zp0 = 0.f, zp1 = 0.f;

    auto row_ptr = [&](int s) -> const RowT* {
        if constexpr (HALF_SRC)
            return (const RowT*)((const __half*)srcv + (size_t)s * F + lane * V);
        else
            return (const RowT*)((const float*)srcv + (size_t)s * F + lane * V);
    };

    auto accum = [&](RowT u, float p0, float p1) {
        if constexpr (HALF_SRC) {
            if constexpr (V == 2) {
                float2 f = __half22float2(*(__half2*)&u);
                acc0[0] += p0 * f.x; acc0[1] += p0 * f.y;
                acc1[0] += p1 * f.x; acc1[1] += p1 * f.y;
            } else {
                float2 f0 = __half22float2(*(__half2*)&u.x);
                float2 f1 = __half22float2(*(__half2*)&u.y);
                acc0[0] += p0 * f0.x; acc0[1] += p0 * f0.y;
                acc0[2] += p0 * f1.x; acc0[3] += p0 * f1.y;
                acc1[0] += p1 * f0.x; acc1[1] += p1 * f0.y;
                acc1[2] += p1 * f1.x; acc1[3] += p1 * f1.y;
            }
        } else {
            if constexpr (V == 2) {
                acc0[0] += p0 * u.x; acc0[1] += p0 * u.y;
                acc1[0] += p1 * u.x; acc1[1] += p1 * u.y;
            } else {
                acc0[0] += p0 * u.x; acc0[1] += p0 * u.y;
                acc0[2] += p0 * u.z; acc0[3] += p0 * u.w;
                acc1[0] += p1 * u.x; acc1[1] += p1 * u.y;
                acc1[2] += p1 * u.z; acc1[3] += p1 * u.w;
            }
        }
    };

    {   // self loop
        float2 a = as2[node];
        float e0 = a.x + adi.x; e0 = e0 > 0.f ? e0 : 0.2f * e0;
        float e1 = a.y + adi.y; e1 = e1 > 0.f ? e1 : 0.2f * e1;
        float p0 = __expf(e0), p1 = __expf(e1);
        if (lane == 0) { zp0 += p0; zp1 += p1; }
        accum(*row_ptr(node), p0, p1);
    }

    for (int j0 = 0; j0 < deg; j0 += 32) {
        const int nb = min(32, deg - j0);
        int sl = 0; float p0 = 0.f, p1 = 0.f;
        if (lane < nb) {
            sl = g_col[base + j0 + lane];
            float2 a = as2[sl];
            float e0 = a.x + adi.x; e0 = e0 > 0.f ? e0 : 0.2f * e0;
            float e1 = a.y + adi.y; e1 = e1 > 0.f ? e1 : 0.2f * e1;
            p0 = __expf(e0); p1 = __expf(e1);
        }
        zp0 += p0; zp1 += p1;
        if (nb == 32) {
            #pragma unroll 8
            for (int k = 0; k < 32; k++) {
                int sk = __shfl_sync(0xffffffffu, sl, k);
                float q0 = __shfl_sync(0xffffffffu, p0, k);
                float q1 = __shfl_sync(0xffffffffu, p1, k);
                accum(*row_ptr(sk), q0, q1);
            }
        } else {
            for (int k = 0; k < nb; k++) {
                int sk = __shfl_sync(0xffffffffu, sl, k);
                float q0 = __shfl_sync(0xffffffffu, p0, k);
                float q1 = __shfl_sync(0xffffffffu, p1, k);
                accum(*row_ptr(sk), q0, q1);
            }
        }
    }

    #pragma unroll
    for (int o = 16; o; o >>= 1) {
        zp0 += __shfl_xor_sync(0xffffffffu, zp0, o);
        zp1 += __shfl_xor_sync(0xffffffffu, zp1, o);
    }
    const float i0 = 1.f / zp0, i1 = 1.f / zp1;

    if constexpr (V == 2) {
        __half h0, l0, h1, l1, h2, l2, h3, l3;
        split16(acc0[0] * i0, h0, l0);
        split16(acc0[1] * i0, h1, l1);
        split16(acc1[0] * i1, h2, l2);
        split16(acc1[1] * i1, h3, l3);
        size_t off0 = (size_t)node * 2 * F + lane * 2;
        size_t off1 = off0 + F;
        *(__half2*)(yhi + off0) = __halves2half2(h0, h1);
        *(__half2*)(yhi + off1) = __halves2half2(h2, h3);
        *(__half2*)(ylo + off0) = __halves2half2(l0, l1);
        *(__half2*)(ylo + off1) = __halves2half2(l2, l3);
    } else {
        float v0[4], v1[4];
        #pragma unroll
        for (int v = 0; v < 4; v++) { v0[v] = acc0[v] * i0; v1[v] = acc1[v] * i1; }
        __half h[8], l[8];
        #pragma unroll
        for (int v = 0; v < 4; v++) split16(v0[v], h[v], l[v]);
        #pragma unroll
        for (int v = 0; v < 4; v++) split16(v1[v], h[4 + v], l[4 + v]);
        size_t off0 = (size_t)node * 2 * F + lane * 4;
        size_t off1 = off0 + F;
        *(uint2*)(yhi + off0) = *(uint2*)&h[0];
        *(uint2*)(yhi + off1) = *(uint2*)&h[4];
        *(uint2*)(ylo + off0) = *(uint2*)&l[0];
        *(uint2*)(ylo + off1) = *(uint2*)&l[4];
    }
}

// ------- shared MMA gemm: smem-staged split-fp16, + BN stats + finalize -----
// MW = m-warps (TM = MW*32); 8/MW n-warps cover 64 N columns.
template <int K, int LD, int NY, int PAD, int MW>
__global__ __launch_bounds__(256) void gemm_mma_kernel(
    const __half* __restrict__ Ahi, const __half* __restrict__ Alo,
    const __half* __restrict__ Whi, const __half* __restrict__ Wlo,
    const float* __restrict__ bias, const float* __restrict__ gamma,
    const float* __restrict__ beta, float* __restrict__ C)
{
    constexpr int TM = MW * 32;          // block M tile
    constexpr int NWN = 8 / MW;          // n-warps
    constexpr int WN = 64 / NWN;         // warp n width
    constexpr int NI = WN / 8;           // n fragments per warp
    extern __shared__ __half sm[];
    __half* sAhi = sm;
    __half* sAlo = sm + TM * PAD;
    __half* sBhi = sm + 2 * TM * PAD;
    __half* sBlo = sBhi + 64 * PAD;
    __shared__ float s_s[64], s_q[64];

    const int tid = threadIdx.x;
    const int warp = tid >> 5, lane = tid & 31;
    const int mw = warp % MW;
    const int nw = warp / MW;
    const int head = (NY == 2) ? (int)blockIdx.y : ((int)blockIdx.y >> 1);
    const int nb = (NY == 2) ? 0 : ((int)blockIdx.y & 1);
    const int row0b = blockIdx.x * TM;
    const int cbA = head * K;
    const int cbC = head * (LD / 2) + nb * 64;
    const int g = lane >> 2;
    const int tk = (lane & 3) * 2;
    if (tid < 64) { s_s[tid] = 0.f; s_q[tid] = 0.f; }

    constexpr int AU = TM * K / 8;
    #pragma unroll
    for (int i = tid; i < AU; i += 256) {
        int r = i / (K / 8);
        int c8 = (i % (K / 8)) * 8;
        int gr = row0b + r;
        uint4 vh = make_uint4(0u, 0u, 0u, 0u);
        uint4 vl = vh;
        if (gr < NN) {
            vh = *(const uint4*)(Ahi + (size_t)gr * LD + cbA + c8);
            vl = *(const uint4*)(Alo + (size_t)gr * LD + cbA + c8);
        }
        *(uint4*)(sAhi + r * PAD + c8) = vh;
        *(uint4*)(sAlo + r * PAD + c8) = vl;
    }
    constexpr int BU = 64 * K / 8;
    #pragma unroll
    for (int i = tid; i < BU; i += 256) {
        int n = i / (K / 8);
        int c8 = (i % (K / 8)) * 8;
        uint4 vh = *(const uint4*)(Whi + (size_t)(cbC + n) * K + c8);
        uint4 vl = *(const uint4*)(Wlo + (size_t)(cbC + n) * K + c8);
        *(uint4*)(sBhi + n * PAD + c8) = vh;
        *(uint4*)(sBlo + n * PAD + c8) = vl;
    }
    __syncthreads();

    float acc[2][NI][4];
    #pragma unroll
    for (int mi = 0; mi < 2; mi++)
        #pragma unroll
        for (int ni = 0; ni < NI; ni++)
            #pragma unroll
            for (int j = 0; j < 4; j++) acc[mi][ni][j] = 0.f;

    #pragma unroll 1
    for (int k0 = 0; k0 < K; k0 += 16) {
        unsigned ah[2][4], al[2][4];
        #pragma unroll
        for (int mi = 0; mi < 2; mi++) {
            int row = mw * 32 + mi * 16 + g;
            const __half* p = sAhi + row * PAD + k0 + tk;
            const __half* q = sAlo + row * PAD + k0 + tk;
            ah[mi][0] = *(const unsigned*)p;
            ah[mi][1] = *(const unsigned*)(p + 8 * PAD);
            ah[mi][2] = *(const unsigned*)(p + 8);
            ah[mi][3] = *(const unsigned*)(p + 8 * PAD + 8);
            al[mi][0] = *(const unsigned*)q;
            al[mi][1] = *(const unsigned*)(q + 8 * PAD);
            al[mi][2] = *(const unsigned*)(q + 8);
            al[mi][3] = *(const unsigned*)(q + 8 * PAD + 8);
        }
        unsigned bh[NI][2], bl[NI][2];
        #pragma unroll
        for (int ni = 0; ni < NI; ni++) {
            int n = nw * WN + ni * 8 + g;
            const __half* p = sBhi + n * PAD + k0 + tk;
            const __half* q = sBlo + n * PAD + k0 + tk;
            bh[ni][0] = *(const unsigned*)p;
            bh[ni][1] = *(const unsigned*)(p + 8);
            bl[ni][0] = *(const unsigned*)q;
            bl[ni][1] = *(const unsigned*)(q + 8);
        }
        #pragma unroll
        for (int mi = 0; mi < 2; mi++)
            #pragma unroll
            for (int ni = 0; ni < NI; ni++) {
                mma16816(acc[mi][ni], ah[mi], bh[ni]);
                mma16816(acc[mi][ni], al[mi], bh[ni]);
                mma16816(acc[mi][ni], ah[mi], bl[ni]);
            }
    }
    __syncthreads();
    const int nbase = cbC + nw * WN;
    #pragma unroll
    for (int ni = 0; ni < NI; ni++) {
        const int col = nbase + ni * 8 + tk;
        float2 bv = *(const float2*)&bias[col];
        float s0 = 0.f, s1 = 0.f, q0 = 0.f, q1 = 0.f;
        #pragma unroll
        for (int mi = 0; mi < 2; mi++) {
            int r0 = row0b + mw * 32 + mi * 16 + g;
            int r1 = r0 + 8;
            float c0 = acc[mi][ni][0] + bv.x;
            float c1 = acc[mi][ni][1] + bv.y;
            float c2 = acc[mi][ni][2] + bv.x;
            float c3 = acc[mi][ni][3] + bv.y;
            if (r0 < NN) {
                *(float2*)&C[(size_t)r0 * LD + col] = make_float2(c0, c1);
                s0 += c0; s1 += c1; q0 += c0 * c0; q1 += c1 * c1;
            }
            if (r1 < NN) {
                *(float2*)&C[(size_t)r1 * LD + col] = make_float2(c2, c3);
                s0 += c2; s1 += c3; q0 += c2 * c2; q1 += c3 * c3;
            }
        }
        #pragma unroll
        for (int o = 4; o < 32; o <<= 1) {
            s0 += __shfl_xor_sync(0xffffffffu, s0, o);
            s1 += __shfl_xor_sync(0xffffffffu, s1, o);
            q0 += __shfl_xor_sync(0xffffffffu, q0, o);
            q1 += __shfl_xor_sync(0xffffffffu, q1, o);
        }
        if (g == 0) {
            int cl = nw * WN + ni * 8 + tk;
            atomicAdd(&s_s[cl], s0);     atomicAdd(&s_s[cl + 1], s1);
            atomicAdd(&s_q[cl], q0);     atomicAdd(&s_q[cl + 1], q1);
        }
    }
    __syncthreads();
    if (tid < 64) {
        g_part[blockIdx.x * 2 * LD + cbC + tid] = s_s[tid];
        g_part[blockIdx.x * 2 * LD + LD + cbC + tid] = s_q[tid];
    }
    __shared__ int last;
    __threadfence();
    __syncthreads();
    if (tid == 0)
        last = (atomicAdd(&g_tick, 1) == (int)(gridDim.x * gridDim.y) - 1);
    __syncthreads();
    if (!last) return;
    for (int col = tid; col < LD; col += 256) {
        float s = 0.f, q = 0.f;
        for (int b = 0; b < (int)gridDim.x; b++) {
            s += g_part[b * 2 * LD + col];
            q += g_part[b * 2 * LD + LD + col];
        }
        const float mu = s * (1.f / NN);
        const float var = q * (1.f / NN) - mu * mu;
        const float sc = gamma[col] * rsqrtf(var + 1e-5f);
        g_scale[col] = sc;
        g_shift[col] = beta[col] - mu * sc;
    }
    if (tid == 0) g_tick = 0;
}

__global__ void bnapply_kernel(const float4* __restrict__ X,
                               float4* __restrict__ Y, int total4) {
    int i = blockIdx.x * blockDim.x + threadIdx.x;
    if (i >= total4) return;
    int c = (i & 63) * 4;
    float4 v = X[i];
    float4 sc = *(const float4*)&g_scale[c];
    float4 sh = *(const float4*)&g_shift[c];
    v.x = fmaxf(v.x * sc.x + sh.x, 0.f);
    v.y = fmaxf(v.y * sc.y + sh.y, 0.f);
    v.z = fmaxf(v.z * sc.z + sh.z, 0.f);
    v.w = fmaxf(v.w * sc.w + sh.w, 0.f);
    Y[i] = v;
}

// ------------------------------- launcher -----------------------------------
extern "C" void kernel_launch(void* const* d_in, const int* in_sizes, int n_in,
                              void* d_out, int out_size) {
    const float* x        = (const float*)d_in[0];
    const void*  ei       = d_in[1];
    const float* W1       = (const float*)d_in[2];
    const float* att_src1 = (const float*)d_in[3];
    const float* att_dst1 = (const float*)d_in[4];
    const float* bias1    = (const float*)d_in[5];
    const float* gamma1   = (const float*)d_in[6];
    const float* beta1    = (const float*)d_in[7];
    const float* W2       = (const float*)d_in[8];
    const float* att_src2 = (const float*)d_in[9];
    const float* att_dst2 = (const float*)d_in[10];
    const float* bias2    = (const float*)d_in[11];
    const float* gamma2   = (const float*)d_in[12];
    const float* beta2    = (const float*)d_in[13];
    float* out = (float*)d_out;

    __half *h16, *y1hi, *y1lo, *y2hi, *y2lo, *w1hi, *w1lo, *w2hi, *w2lo;
    float *out1, *out2, *as1, *ad1, *as2, *ad2;
    float4 *u1, *u2;
    cudaGetSymbolAddress((void**)&h16,  g_h16);
    cudaGetSymbolAddress((void**)&y1hi, g_y1hi);
    cudaGetSymbolAddress((void**)&y1lo, g_y1lo);
    cudaGetSymbolAddress((void**)&y2hi, g_y2hi);
    cudaGetSymbolAddress((void**)&y2lo, g_y2lo);
    cudaGetSymbolAddress((void**)&w1hi, g_w1hi);
    cudaGetSymbolAddress((void**)&w1lo, g_w1lo);
    cudaGetSymbolAddress((void**)&w2hi, g_w2hi);
    cudaGetSymbolAddress((void**)&w2lo, g_w2lo);
    cudaGetSymbolAddress((void**)&out1, g_out1);
    cudaGetSymbolAddress((void**)&out2, g_out2);
    cudaGetSymbolAddress((void**)&as1,  g_as1);
    cudaGetSymbolAddress((void**)&ad1,  g_ad1);
    cudaGetSymbolAddress((void**)&as2,  g_as2);
    cudaGetSymbolAddress((void**)&ad2,  g_ad2);
    cudaGetSymbolAddress((void**)&u1,   g_u1);
    cudaGetSymbolAddress((void**)&u2,   g_u2);

    cudaFuncSetAttribute((const void*)gemm_mma_kernel<64, 128, 2, PAD1, 2>,
                         cudaFuncAttributeMaxDynamicSharedMemorySize,
                         SM1_BYTES);
    cudaFuncSetAttribute((const void*)gemm_mma_kernel<128, 256, 4, PAD2, 4>,
                         cudaFuncAttributeMaxDynamicSharedMemorySize,
                         SM2_BYTES);

    prep_kernel<<<HB + 64, 256>>>(ei, W1, att_src1, att_dst1,
                                  W2, att_src2, att_dst2);
    rowptr_kernel<<<CB, 256>>>();
    scatter_gemv1_kernel<<<HB + NN / 8, 256>>>(ei, x, u1, as1, ad1);

    agg_kernel<64, false><<<NN / 8, 256>>>(x, as1, ad1, y1hi, y1lo);
    gemm_mma_kernel<64, 128, 2, PAD1, 2><<<dim3(GB1, 2), 256, SM1_BYTES>>>(
        y1hi, y1lo, w1hi, w1lo, bias1, gamma1, beta1, out1);
    gemv2_kernel<<<NN / 8, 256>>>(out1, u2, as2, ad2, h16);
    agg_kernel<128, true><<<NN / 8, 256>>>(h16, as2, ad2, y2hi, y2lo);
    gemm_mma_kernel<128, 256, 4, PAD2, 4><<<dim3(GB2, 4), 256, SM2_BYTES>>>(
        y2hi, y2lo, w2hi, w2lo, bias2, gamma2, beta2, out2);
    bnapply_kernel<<<(NN * 64 + 255) / 256, 256>>>((const float4*)out2,
                                                   (float4*)out, NN * 64);
}

// round 16
// speedup vs baseline: 1.1048x; 1.1048x over previous
#include <cuda_runtime.h>
#include <cuda_fp16.h>
#include <cuda_bf16.h>
#include <math.h>
#include <type_traits>

// ---------------------------------------------------------------------------
// GATLayers round 16 = R13 champion (135.9us) verbatim + batch-level col
// prefetch in agg (overlaps next batch's g_col LDG under current batch work).
// R14/R15 structural changes retired (regressed / noise-dominated).
// ---------------------------------------------------------------------------

constexpr int NN = 20000;
constexpr int EE = 640000;
constexpr int CB = (NN + 255) / 256;   // 79 scan blocks
constexpr int HB = EE / 256;           // 2500 hist/scatter blocks
constexpr int GB2 = (NN + 127) / 128;  // 157 mma row-blocks
constexpr int PAD2 = 136;              // gemm2 smem row stride (halves)
constexpr int PAD1 = 72;               // gemm1 smem row stride (halves)
constexpr int SM2_BYTES = (2 * 128 * PAD2 + 2 * 64 * PAD2) * 2;  // 104448
constexpr int SM1_BYTES = (2 * 128 * PAD1 + 2 * 64 * PAD1) * 2;  // 55296

// ------------------------------ scratch ------------------------------------
__device__ int    g_is64;
__device__ int    g_ready;
__device__ int    g_done;
__device__ int    g_tick;
__device__ int    g_deg[NN];
__device__ int    g_rowptr[NN + 1];
__device__ int    g_rank[EE];
__device__ int    g_col[EE];
__device__ int    g_bsum[CB];
__device__ __half g_h16[NN * 128];     // relu(bn(out1)) fp16
__device__ __half g_w1hi[128 * 64];    // W1^T hi fp16: [n][k]
__device__ __half g_w1lo[128 * 64];
__device__ __half g_w2hi[256 * 128];   // W2^T hi fp16: [n][k]
__device__ __half g_w2lo[256 * 128];
__device__ __half g_y1hi[NN * 128];    // aggregated layer1 hi
__device__ __half g_y1lo[NN * 128];
__device__ __half g_y2hi[NN * 256];    // aggregated layer2 hi
__device__ __half g_y2lo[NN * 256];
__device__ float  g_out1[NN * 128];
__device__ float  g_out2[NN * 256];
__device__ float  g_as1[NN * 2];
__device__ float  g_ad1[NN * 2];
__device__ float  g_as2[NN * 2];
__device__ float  g_ad2[NN * 2];
__device__ float  g_part[GB2 * 2 * 256];
__device__ float  g_scale[256];
__device__ float  g_shift[256];
__device__ float4 g_u1[64];
__device__ float4 g_u2[128];

// ------------------------------ helpers -------------------------------------
__device__ __forceinline__ void split16(float v, __half& h, __half& l) {
    h = __float2half_rn(v);
    l = __float2half_rn(v - __half2float(h));
}
__device__ __forceinline__ int edge_val(const void* ei, int idx, int is64) {
    if (is64) return (int)((const long long*)ei)[idx];
    return ((const int*)ei)[idx];
}
__device__ __forceinline__ void mma16816(
    float* c, const unsigned* a, const unsigned* b)
{
    asm volatile(
        "mma.sync.aligned.m16n8k16.row.col.f32.f16.f16.f32 "
        "{%0,%1,%2,%3}, {%4,%5,%6,%7}, {%8,%9}, {%0,%1,%2,%3};"
        : "+f"(c[0]), "+f"(c[1]), "+f"(c[2]), "+f"(c[3])
        : "r"(a[0]), "r"(a[1]), "r"(a[2]), "r"(a[3]), "r"(b[0]), "r"(b[1]));
}

// -------- prep: hist (per-block is64) + attvec + W2/W1 split-fp16 -----------
__global__ __launch_bounds__(256) void prep_kernel(
    const void* __restrict__ ei,
    const float* __restrict__ W1, const float* __restrict__ s1,
    const float* __restrict__ d1,
    const float* __restrict__ W2, const float* __restrict__ s2,
    const float* __restrict__ d2)
{
    const int bx = blockIdx.x;
    const int tid = threadIdx.x;
    if (bx < HB) {
        const int* ei32 = (const int*)ei;
        __shared__ int s_is64;
        if (tid < 32) {
            int a = ei32[2 * tid + 1];
            int b = ei32[2 * (tid + 32) + 1];
            unsigned m = __ballot_sync(0xffffffffu, (a | b) != 0);
            if (tid == 0) {
                s_is64 = (m == 0) ? 1 : 0;
                if (bx == 0) g_is64 = s_is64;
            }
        }
        __syncthreads();
        const int is64 = s_is64;
        int e = bx * 256 + tid;
        int dst = edge_val(ei, EE + e, is64);
        g_rank[e] = atomicAdd(&g_deg[dst], 1);
        return;
    }
    if (bx < HB + 24) {    // attention vectors
        const int lane = tid & 31;
        const int f = (bx - HB) * 8 + (tid >> 5);   // 0..191
        float4 u = make_float4(0.f, 0.f, 0.f, 0.f);
        if (f < 64) {
            #pragma unroll
            for (int c = lane; c < 64; c += 32) {
                float w0 = W1[f * 128 + c], w1 = W1[f * 128 + 64 + c];
                u.x += w0 * s1[c];      u.y += w1 * s1[64 + c];
                u.z += w0 * d1[c];      u.w += w1 * d1[64 + c];
            }
        } else {
            int f2 = f - 64;
            #pragma unroll
            for (int c = lane; c < 128; c += 32) {
                float w0 = W2[f2 * 256 + c], w1 = W2[f2 * 256 + 128 + c];
                u.x += w0 * s2[c];      u.y += w1 * s2[128 + c];
                u.z += w0 * d2[c];      u.w += w1 * d2[128 + c];
            }
        }
        #pragma unroll
        for (int o = 16; o; o >>= 1) {
            u.x += __shfl_xor_sync(0xffffffffu, u.x, o);
            u.y += __shfl_xor_sync(0xffffffffu, u.y, o);
            u.z += __shfl_xor_sync(0xffffffffu, u.z, o);
            u.w += __shfl_xor_sync(0xffffffffu, u.w, o);
        }
        if (lane == 0) {
            if (f < 64) g_u1[f] = u;
            else        g_u2[f - 64] = u;
        }
        return;
    }
    if (bx < HB + 56) {   // W2^T split: 32 blocks
        int t4 = (bx - HB - 24) * 256 + tid;
        int e = t4 * 4;
        int k = e >> 8;
        int n0 = e & 255;
        float4 w = *(const float4*)&W2[k * 256 + n0];
        __half h, l;
        split16(w.x, h, l); g_w2hi[(n0 + 0) * 128 + k] = h; g_w2lo[(n0 + 0) * 128 + k] = l;
        split16(w.y, h, l); g_w2hi[(n0 + 1) * 128 + k] = h; g_w2lo[(n0 + 1) * 128 + k] = l;
        split16(w.z, h, l); g_w2hi[(n0 + 2) * 128 + k] = h; g_w2lo[(n0 + 2) * 128 + k] = l;
        split16(w.w, h, l); g_w2hi[(n0 + 3) * 128 + k] = h; g_w2lo[(n0 + 3) * 128 + k] = l;
        return;
    }
    {   // W1^T split: 8 blocks
        int t4 = (bx - HB - 56) * 256 + tid;
        int e = t4 * 4;
        int k = e >> 7;
        int n0 = e & 127;
        float4 w = *(const float4*)&W1[k * 128 + n0];
        __half h, l;
        split16(w.x, h, l); g_w1hi[(n0 + 0) * 64 + k] = h; g_w1lo[(n0 + 0) * 64 + k] = l;
        split16(w.y, h, l); g_w1hi[(n0 + 1) * 64 + k] = h; g_w1lo[(n0 + 1) * 64 + k] = l;
        split16(w.z, h, l); g_w1hi[(n0 + 2) * 64 + k] = h; g_w1lo[(n0 + 2) * 64 + k] = l;
        split16(w.w, h, l); g_w1hi[(n0 + 3) * 64 + k] = h; g_w1lo[(n0 + 3) * 64 + k] = l;
    }
}

// ----------------- rowptr: scan + spin + deg reset for next replay ----------
__global__ __launch_bounds__(256) void rowptr_kernel() {
    __shared__ int s[256];
    const int t = threadIdx.x;
    const int bx = blockIdx.x;
    const int i = bx * 256 + t;
    int d = (i < NN) ? g_deg[i] : 0;
    if (i < NN) g_deg[i] = 0;
    s[t] = d;
    __syncthreads();
    for (int o = 1; o < 256; o <<= 1) {
        int u = (t >= o) ? s[t - o] : 0;
        __syncthreads();
        s[t] += u;
        __syncthreads();
    }
    const int incl = s[t];
    if (t == 255) {
        g_bsum[bx] = incl;
        __threadfence();
        atomicAdd(&g_ready, 1);
        while (atomicAdd(&g_ready, 0) < (int)gridDim.x) {}
    }
    __syncthreads();
    int pre = 0;
    for (int b = t; b < bx; b += 256) pre += g_bsum[b];
    #pragma unroll
    for (int o = 16; o; o >>= 1) pre += __shfl_xor_sync(0xffffffffu, pre, o);
    __shared__ int ws[8];
    if ((t & 31) == 0) ws[t >> 5] = pre;
    __syncthreads();
    if (t == 0) {
        int p = 0;
        #pragma unroll
        for (int w = 0; w < 8; w++) p += ws[w];
        s[0] = p;
    }
    __syncthreads();
    const int bpre = s[0];
    if (i < NN) g_rowptr[i] = bpre + incl - d;
    if (i == NN - 1) g_rowptr[NN] = bpre + incl;
    if (t == 0 && atomicAdd(&g_done, 1) == (int)gridDim.x - 1) {
        g_ready = 0;
        g_done = 0;
    }
}

// --------------------------- score GEMV body --------------------------------
template <int K, bool BN>
__device__ __forceinline__ void gemv_body(
    int node, const float* __restrict__ A, const float4* __restrict__ U,
    float* __restrict__ as_out, float* __restrict__ ad_out,
    __half* __restrict__ h16, int lane)
{
    float4 acc = make_float4(0.f, 0.f, 0.f, 0.f);
    #pragma unroll
    for (int f = lane; f < K; f += 32) {
        float v = A[(size_t)node * K + f];
        if (BN) {
            v = v * g_scale[f] + g_shift[f];
            v = v > 0.f ? v : 0.f;
            h16[(size_t)node * K + f] = __float2half_rn(v);
        }
        float4 u = U[f];
        acc.x += v * u.x; acc.y += v * u.y;
        acc.z += v * u.z; acc.w += v * u.w;
    }
    #pragma unroll
    for (int o = 16; o; o >>= 1) {
        acc.x += __shfl_xor_sync(0xffffffffu, acc.x, o);
        acc.y += __shfl_xor_sync(0xffffffffu, acc.y, o);
        acc.z += __shfl_xor_sync(0xffffffffu, acc.z, o);
        acc.w += __shfl_xor_sync(0xffffffffu, acc.w, o);
    }
    if (lane == 0) {
        as_out[node * 2 + 0] = acc.x;
        as_out[node * 2 + 1] = acc.y;
        ad_out[node * 2 + 0] = acc.z;
        ad_out[node * 2 + 1] = acc.w;
    }
}

__global__ __launch_bounds__(256) void scatter_gemv1_kernel(
    const void* __restrict__ ei, const float* __restrict__ x,
    const float4* __restrict__ U,
    float* __restrict__ as_out, float* __restrict__ ad_out)
{
    const int bx = blockIdx.x;
    if (bx < HB) {
        int e = bx * 256 + threadIdx.x;
        int is64 = g_is64;
        int src = edge_val(ei, e, is64);
        int dst = edge_val(ei, EE + e, is64);
        g_col[g_rowptr[dst] + g_rank[e]] = src;
        return;
    }
    const int node = (bx - HB) * 8 + (threadIdx.x >> 5);
    gemv_body<64, false>(node, x, U, as_out, ad_out, nullptr,
                         threadIdx.x & 31);
}

__global__ __launch_bounds__(256) void gemv2_kernel(
    const float* __restrict__ A, const float4* __restrict__ U,
    float* __restrict__ as_out, float* __restrict__ ad_out,
    __half* __restrict__ h16)
{
    const int node = blockIdx.x * 8 + (threadIdx.x >> 5);
    gemv_body<128, true>(node, A, U, as_out, ad_out, h16, threadIdx.x & 31);
}

// ------------------- segment softmax + weighted aggregate ------------------
// Batched-32 edges per warp. HALF_SRC: fp16 rows (layer 2) vs fp32 (layer 1).
// Next batch's column indices are prefetched under the current batch's work.
template <int F, bool HALF_SRC>
__global__ __launch_bounds__(256) void agg_kernel(
    const void* __restrict__ srcv, const float* __restrict__ as,
    const float* __restrict__ ad,
    __half* __restrict__ yhi, __half* __restrict__ ylo)
{
    const int lane = threadIdx.x & 31;
    const int warp = threadIdx.x >> 5;
    const int node = blockIdx.x * 8 + warp;
    constexpr int V = F / 32;   // elems per lane: 2 or 4
    using RowT = typename std::conditional<
        HALF_SRC, typename std::conditional<V == 2, unsigned, uint2>::type,
                  typename std::conditional<V == 2, float2, float4>::type>::type;
    const int base = g_rowptr[node];
    const int deg = g_rowptr[node + 1] - base;
    const float2* as2 = (const float2*)as;
    const float2 adi = ((const float2*)ad)[node];

    float acc0[V], acc1[V];
    #pragma unroll
    for (int v = 0; v < V; v++) { acc0[v] = 0.f; acc1[v] = 0.f; }
    float zp0 = 0.f, zp1 = 0.f;

    auto row_ptr = [&](int s) -> const RowT* {
        if constexpr (HALF_SRC)
            return (const RowT*)((const __half*)srcv + (size_t)s * F + lane * V);
        else
            return (const RowT*)((const float*)srcv + (size_t)s * F + lane * V);
    };

    auto accum = [&](RowT u, float p0, float p1) {
        if constexpr (HALF_SRC) {
            if constexpr (V == 2) {
                float2 f = __half22float2(*(__half2*)&u);
                acc0[0] += p0 * f.x; acc0[1] += p0 * f.y;
                acc1[0] += p1 * f.x; acc1[1] += p1 * f.y;
            } else {
                float2 f0 = __half22float2(*(__half2*)&u.x);
                float2 f1 = __half22float2(*(__half2*)&u.y);
                acc0[0] += p0 * f0.x; acc0[1] += p0 * f0.y;
                acc0[2] += p0 * f1.x; acc0[3] += p0 * f1.y;
                acc1[0] += p1 * f0.x; acc1[1] += p1 * f0.y;
                acc1[2] += p1 * f1.x; acc1[3] += p1 * f1.y;
            }
        } else {
            if constexpr (V == 2) {
                acc0[0] += p0 * u.x; acc0[1] += p0 * u.y;
                acc1[0] += p1 * u.x; acc1[1] += p1 * u.y;
            } else {
                acc0[0] += p0 * u.x; acc0[1] += p0 * u.y;
                acc0[2] += p0 * u.z; acc0[3] += p0 * u.w;
                acc1[0] += p1 * u.x; acc1[1] += p1 * u.y;
                acc1[2] += p1 * u.z; acc1[3] += p1 * u.w;
            }
        }
    };

    {   // self loop
        float2 a = as2[node];
        float e0 = a.x + adi.x; e0 = e0 > 0.f ? e0 : 0.2f * e0;
        float e1 = a.y + adi.y; e1 = e1 > 0.f ? e1 : 0.2f * e1;
        float p0 = __expf(e0), p1 = __expf(e1);
        if (lane == 0) { zp0 += p0; zp1 += p1; }
        accum(*row_ptr(node), p0, p1);
    }

    // prefetch first batch's column indices
    int sl = 0;
    if (deg > 0 && lane < min(32, deg)) sl = g_col[base + lane];

    for (int j0 = 0; j0 < deg; j0 += 32) {
        const int nb = min(32, deg - j0);
        // prefetch next batch's cols before this batch's scoring/accumulate
        int sl_next = 0;
        {
            int rem = deg - j0 - 32;
            if (rem > 0 && lane < min(32, rem))
                sl_next = g_col[base + j0 + 32 + lane];
        }
        float p0 = 0.f, p1 = 0.f;
        if (lane < nb) {
            float2 a = as2[sl];
            float e0 = a.x + adi.x; e0 = e0 > 0.f ? e0 : 0.2f * e0;
            float e1 = a.y + adi.y; e1 = e1 > 0.f ? e1 : 0.2f * e1;
            p0 = __expf(e0); p1 = __expf(e1);
        }
        zp0 += p0; zp1 += p1;
        if (nb == 32) {
            #pragma unroll 8
            for (int k = 0; k < 32; k++) {
                int sk = __shfl_sync(0xffffffffu, sl, k);
                float q0 = __shfl_sync(0xffffffffu, p0, k);
                float q1 = __shfl_sync(0xffffffffu, p1, k);
                accum(*row_ptr(sk), q0, q1);
            }
        } else {
            for (int k = 0; k < nb; k++) {
                int sk = __shfl_sync(0xffffffffu, sl, k);
                float q0 = __shfl_sync(0xffffffffu, p0, k);
                float q1 = __shfl_sync(0xffffffffu, p1, k);
                accum(*row_ptr(sk), q0, q1);
            }
        }
        sl = sl_next;
    }

    #pragma unroll
    for (int o = 16; o; o >>= 1) {
        zp0 += __shfl_xor_sync(0xffffffffu, zp0, o);
        zp1 += __shfl_xor_sync(0xffffffffu, zp1, o);
    }
    const float i0 = 1.f / zp0, i1 = 1.f / zp1;

    if constexpr (V == 2) {
        __half h0, l0, h1, l1, h2, l2, h3, l3;
        split16(acc0[0] * i0, h0, l0);
        split16(acc0[1] * i0, h1, l1);
        split16(acc1[0] * i1, h2, l2);
        split16(acc1[1] * i1, h3, l3);
        size_t off0 = (size_t)node * 2 * F + lane * 2;
        size_t off1 = off0 + F;
        *(__half2*)(yhi + off0) = __halves2half2(h0, h1);
        *(__half2*)(yhi + off1) = __halves2half2(h2, h3);
        *(__half2*)(ylo + off0) = __halves2half2(l0, l1);
        *(__half2*)(ylo + off1) = __halves2half2(l2, l3);
    } else {
        float v0[4], v1[4];
        #pragma unroll
        for (int v = 0; v < 4; v++) { v0[v] = acc0[v] * i0; v1[v] = acc1[v] * i1; }
        __half h[8], l[8];
        #pragma unroll
        for (int v = 0; v < 4; v++) split16(v0[v], h[v], l[v]);
        #pragma unroll
        for (int v = 0; v < 4; v++) split16(v1[v], h[4 + v], l[4 + v]);
        size_t off0 = (size_t)node * 2 * F + lane * 4;
        size_t off1 = off0 + F;
        *(uint2*)(yhi + off0) = *(uint2*)&h[0];
        *(uint2*)(yhi + off1) = *(uint2*)&h[4];
        *(uint2*)(ylo + off0) = *(uint2*)&l[0];
        *(uint2*)(ylo + off1) = *(uint2*)&l[4];
    }
}

// ------- shared MMA gemm: smem-staged split-fp16, + BN stats + finalize -----
template <int K, int LD, int NY, int PAD>
__global__ __launch_bounds__(256) void gemm_mma_kernel(
    const __half* __restrict__ Ahi, const __half* __restrict__ Alo,
    const __half* __restrict__ Whi, const __half* __restrict__ Wlo,
    const float* __restrict__ bias, const float* __restrict__ gamma,
    const float* __restrict__ beta, float* __restrict__ C)
{
    extern __shared__ __half sm[];
    __half* sAhi = sm;
    __half* sAlo = sm + 128 * PAD;
    __half* sBhi = sm + 2 * 128 * PAD;
    __half* sBlo = sBhi + 64 * PAD;
    __shared__ float s_s[64], s_q[64];

    const int tid = threadIdx.x;
    const int warp = tid >> 5, lane = tid & 31;
    const int mw = warp & 3;
    const int nw = warp >> 2;
    const int head = (NY == 2) ? (int)blockIdx.y : ((int)blockIdx.y >> 1);
    const int nb = (NY == 2) ? 0 : ((int)blockIdx.y & 1);
    const int row0b = blockIdx.x * 128;
    const int cbA = head * K;
    const int cbC = head * (LD / 2) + nb * 64;
    const int g = lane >> 2;
    const int tk = (lane & 3) * 2;
    if (tid < 64) { s_s[tid] = 0.f; s_q[tid] = 0.f; }

    constexpr int AU = 128 * K / 8;
    #pragma unroll
    for (int i = tid; i < AU; i += 256) {
        int r = i / (K / 8);
        int c8 = (i % (K / 8)) * 8;
        int gr = row0b + r;
        uint4 vh = make_uint4(0u, 0u, 0u, 0u);
        uint4 vl = vh;
        if (gr < NN) {
            vh = *(const uint4*)(Ahi + (size_t)gr * LD + cbA + c8);
            vl = *(const uint4*)(Alo + (size_t)gr * LD + cbA + c8);
        }
        *(uint4*)(sAhi + r * PAD + c8) = vh;
        *(uint4*)(sAlo + r * PAD + c8) = vl;
    }
    constexpr int BU = 64 * K / 8;
    #pragma unroll
    for (int i = tid; i < BU; i += 256) {
        int n = i / (K / 8);
        int c8 = (i % (K / 8)) * 8;
        uint4 vh = *(const uint4*)(Whi + (size_t)(cbC + n) * K + c8);
        uint4 vl = *(const uint4*)(Wlo + (size_t)(cbC + n) * K + c8);
        *(uint4*)(sBhi + n * PAD + c8) = vh;
        *(uint4*)(sBlo + n * PAD + c8) = vl;
    }
    __syncthreads();

    float acc[2][4][4];
    #pragma unroll
    for (int mi = 0; mi < 2; mi++)
        #pragma unroll
        for (int ni = 0; ni < 4; ni++)
            #pragma unroll
            for (int j = 0; j < 4; j++) acc[mi][ni][j] = 0.f;

    #pragma unroll 1
    for (int k0 = 0; k0 < K; k0 += 16) {
        unsigned ah[2][4], al[2][4];
        #pragma unroll
        for (int mi = 0; mi < 2; mi++) {
            int row = mw * 32 + mi * 16 + g;
            const __half* p = sAhi + row * PAD + k0 + tk;
            const __half* q = sAlo + row * PAD + k0 + tk;
            ah[mi][0] = *(const unsigned*)p;
            ah[mi][1] = *(const unsigned*)(p + 8 * PAD);
            ah[mi][2] = *(const unsigned*)(p + 8);
            ah[mi][3] = *(const unsigned*)(p + 8 * PAD + 8);
            al[mi][0] = *(const unsigned*)q;
            al[mi][1] = *(const unsigned*)(q + 8 * PAD);
            al[mi][2] = *(const unsigned*)(q + 8);
            al[mi][3] = *(const unsigned*)(q + 8 * PAD + 8);
        }
        unsigned bh[4][2], bl[4][2];
        #pragma unroll
        for (int ni = 0; ni < 4; ni++) {
            int n = nw * 32 + ni * 8 + g;
            const __half* p = sBhi + n * PAD + k0 + tk;
            const __half* q = sBlo + n * PAD + k0 + tk;
            bh[ni][0] = *(const unsigned*)p;
            bh[ni][1] = *(const unsigned*)(p + 8);
            bl[ni][0] = *(const unsigned*)q;
            bl[ni][1] = *(const unsigned*)(q + 8);
        }
        #pragma unroll
        for (int mi = 0; mi < 2; mi++)
            #pragma unroll
            for (int ni = 0; ni < 4; ni++) {
                mma16816(acc[mi][ni], ah[mi], bh[ni]);
                mma16816(acc[mi][ni], al[mi], bh[ni]);
                mma16816(acc[mi][ni], ah[mi], bl[ni]);
            }
    }
    __syncthreads();
    const int nbase = cbC + nw * 32;
    #pragma unroll
    for (int ni = 0; ni < 4; ni++) {
        const int col = nbase + ni * 8 + tk;
        float2 bv = *(const float2*)&bias[col];
        float s0 = 0.f, s1 = 0.f, q0 = 0.f, q1 = 0.f;
        #pragma unroll
        for (int mi = 0; mi < 2; mi++) {
            int r0 = row0b + mw * 32 + mi * 16 + g;
            int r1 = r0 + 8;
            float c0 = acc[mi][ni][0] + bv.x;
            float c1 = acc[mi][ni][1] + bv.y;
            float c2 = acc[mi][ni][2] + bv.x;
            float c3 = acc[mi][ni][3] + bv.y;
            if (r0 < NN) {
                *(float2*)&C[(size_t)r0 * LD + col] = make_float2(c0, c1);
                s0 += c0; s1 += c1; q0 += c0 * c0; q1 += c1 * c1;
            }
            if (r1 < NN) {
                *(float2*)&C[(size_t)r1 * LD + col] = make_float2(c2, c3);
                s0 += c2; s1 += c3; q0 += c2 * c2; q1 += c3 * c3;
            }
        }
        #pragma unroll
        for (int o = 4; o < 32; o <<= 1) {
            s0 += __shfl_xor_sync(0xffffffffu, s0, o);
            s1 += __shfl_xor_sync(0xffffffffu, s1, o);
            q0 += __shfl_xor_sync(0xffffffffu, q0, o);
            q1 += __shfl_xor_sync(0xffffffffu, q1, o);
        }
        if (g == 0) {
            int cl = nw * 32 + ni * 8 + tk;
            atomicAdd(&s_s[cl], s0);     atomicAdd(&s_s[cl + 1], s1);
            atomicAdd(&s_q[cl], q0);     atomicAdd(&s_q[cl + 1], q1);
        }
    }
    __syncthreads();
    if (tid < 64) {
        g_part[blockIdx.x * 2 * LD + cbC + tid] = s_s[tid];
        g_part[blockIdx.x * 2 * LD + LD + cbC + tid] = s_q[tid];
    }
    __shared__ int last;
    __threadfence();
    __syncthreads();
    if (tid == 0)
        last = (atomicAdd(&g_tick, 1) == (int)(gridDim.x * gridDim.y) - 1);
    __syncthreads();
    if (!last) return;
    for (int col = tid; col < LD; col += 256) {
        float s = 0.f, q = 0.f;
        for (int b = 0; b < GB2; b++) {
            s += g_part[b * 2 * LD + col];
            q += g_part[b * 2 * LD + LD + col];
        }
        const float mu = s * (1.f / NN);
        const float var = q * (1.f / NN) - mu * mu;
        const float sc = gamma[col] * rsqrtf(var + 1e-5f);
        g_scale[col] = sc;
        g_shift[col] = beta[col] - mu * sc;
    }
    if (tid == 0) g_tick = 0;
}

__global__ void bnapply_kernel(const float4* __restrict__ X,
                               float4* __restrict__ Y, int total4) {
    int i = blockIdx.x * blockDim.x + threadIdx.x;
    if (i >= total4) return;
    int c = (i & 63) * 4;
    float4 v = X[i];
    float4 sc = *(const float4*)&g_scale[c];
    float4 sh = *(const float4*)&g_shift[c];
    v.x = fmaxf(v.x * sc.x + sh.x, 0.f);
    v.y = fmaxf(v.y * sc.y + sh.y, 0.f);
    v.z = fmaxf(v.z * sc.z + sh.z, 0.f);
    v.w = fmaxf(v.w * sc.w + sh.w, 0.f);
    Y[i] = v;
}

// ------------------------------- launcher -----------------------------------
extern "C" void kernel_launch(void* const* d_in, const int* in_sizes, int n_in,
                              void* d_out, int out_size) {
    const float* x        = (const float*)d_in[0];
    const void*  ei       = d_in[1];
    const float* W1       = (const float*)d_in[2];
    const float* att_src1 = (const float*)d_in[3];
    const float* att_dst1 = (const float*)d_in[4];
    const float* bias1    = (const float*)d_in[5];
    const float* gamma1   = (const float*)d_in[6];
    const float* beta1    = (const float*)d_in[7];
    const float* W2       = (const float*)d_in[8];
    const float* att_src2 = (const float*)d_in[9];
    const float* att_dst2 = (const float*)d_in[10];
    const float* bias2    = (const float*)d_in[11];
    const float* gamma2   = (const float*)d_in[12];
    const float* beta2    = (const float*)d_in[13];
    float* out = (float*)d_out;

    __half *h16, *y1hi, *y1lo, *y2hi, *y2lo, *w1hi, *w1lo, *w2hi, *w2lo;
    float *out1, *out2, *as1, *ad1, *as2, *ad2;
    float4 *u1, *u2;
    cudaGetSymbolAddress((void**)&h16,  g_h16);
    cudaGetSymbolAddress((void**)&y1hi, g_y1hi);
    cudaGetSymbolAddress((void**)&y1lo, g_y1lo);
    cudaGetSymbolAddress((void**)&y2hi, g_y2hi);
    cudaGetSymbolAddress((void**)&y2lo, g_y2lo);
    cudaGetSymbolAddress((void**)&w1hi, g_w1hi);
    cudaGetSymbolAddress((void**)&w1lo, g_w1lo);
    cudaGetSymbolAddress((void**)&w2hi, g_w2hi);
    cudaGetSymbolAddress((void**)&w2lo, g_w2lo);
    cudaGetSymbolAddress((void**)&out1, g_out1);
    cudaGetSymbolAddress((void**)&out2, g_out2);
    cudaGetSymbolAddress((void**)&as1,  g_as1);
    cudaGetSymbolAddress((void**)&ad1,  g_ad1);
    cudaGetSymbolAddress((void**)&as2,  g_as2);
    cudaGetSymbolAddress((void**)&ad2,  g_ad2);
    cudaGetSymbolAddress((void**)&u1,   g_u1);
    cudaGetSymbolAddress((void**)&u2,   g_u2);

    cudaFuncSetAttribute((const void*)gemm_mma_kernel<64, 128, 2, PAD1>,
                         cudaFuncAttributeMaxDynamicSharedMemorySize,
                         SM1_BYTES);
    cudaFuncSetAttribute((const void*)gemm_mma_kernel<128, 256, 4, PAD2>,
                         cudaFuncAttributeMaxDynamicSharedMemorySize,
                         SM2_BYTES);

    prep_kernel<<<HB + 64, 256>>>(ei, W1, att_src1, att_dst1,
                                  W2, att_src2, att_dst2);
    rowptr_kernel<<<CB, 256>>>();
    scatter_gemv1_kernel<<<HB + NN / 8, 256>>>(ei, x, u1, as1, ad1);

    agg_kernel<64, false><<<NN / 8, 256>>>(x, as1, ad1, y1hi, y1lo);
    gemm_mma_kernel<64, 128, 2, PAD1><<<dim3(GB2, 2), 256, SM1_BYTES>>>(
        y1hi, y1lo, w1hi, w1lo, bias1, gamma1, beta1, out1);
    gemv2_kernel<<<NN / 8, 256>>>(out1, u2, as2, ad2, h16);
    agg_kernel<128, true><<<NN / 8, 256>>>(h16, as2, ad2, y2hi, y2lo);
    gemm_mma_kernel<128, 256, 4, PAD2><<<dim3(GB2, 4), 256, SM2_BYTES>>>(
        y2hi, y2lo, w2hi, w2lo, bias2, gamma2, beta2, out2);
    bnapply_kernel<<<(NN * 64 + 255) / 256, 256>>>((const float4*)out2,
                                                   (float4*)out, NN * 64);
}

// round 17
// speedup vs baseline: 1.1515x; 1.0422x over previous
#include <cuda_runtime.h>
#include <cuda_fp16.h>
#include <cuda_bf16.h>
#include <math.h>
#include <type_traits>

// ---------------------------------------------------------------------------
// GATLayers FINAL = round-13 champion (measured 135.9us, rel_err 2.49e-4).
// R14 (occupancy forcing + rps fusion), R15 (gemm1 M64 retile), R16 (agg
// col prefetch) all regressed and are reverted; this is the verified best.
// Structure:
//   - aggregate-then-transform: out = (sum alpha*x_src) @ W  (exact algebra)
//   - scores via u = W @ att vectors (exact), warp-GEMV
//   - agg: warp/node, both heads, batched-32 distributed edge scoring,
//     fp32 gather (layer1, issue-bound) / fp16 gather (layer2, L2-bound)
//   - GEMMs: smem-staged split-fp16 tensor-core MMA (near-fp32 exact),
//     fused BN stats + last-block finalize
//   - CSR: fused hist/prep, spin-scan rowptr, fused scatter+gemv1
// ---------------------------------------------------------------------------

constexpr int NN = 20000;
constexpr int EE = 640000;
constexpr int CB = (NN + 255) / 256;   // 79 scan blocks
constexpr int HB = EE / 256;           // 2500 hist/scatter blocks
constexpr int GB2 = (NN + 127) / 128;  // 157 mma row-blocks
constexpr int PAD2 = 136;              // gemm2 smem row stride (halves)
constexpr int PAD1 = 72;               // gemm1 smem row stride (halves)
constexpr int SM2_BYTES = (2 * 128 * PAD2 + 2 * 64 * PAD2) * 2;  // 104448
constexpr int SM1_BYTES = (2 * 128 * PAD1 + 2 * 64 * PAD1) * 2;  // 55296

// ------------------------------ scratch ------------------------------------
__device__ int    g_is64;
__device__ int    g_ready;
__device__ int    g_done;
__device__ int    g_tick;
__device__ int    g_deg[NN];
__device__ int    g_rowptr[NN + 1];
__device__ int    g_rank[EE];
__device__ int    g_col[EE];
__device__ int    g_bsum[CB];
__device__ __half g_h16[NN * 128];     // relu(bn(out1)) fp16
__device__ __half g_w1hi[128 * 64];    // W1^T hi fp16: [n][k]
__device__ __half g_w1lo[128 * 64];
__device__ __half g_w2hi[256 * 128];   // W2^T hi fp16: [n][k]
__device__ __half g_w2lo[256 * 128];
__device__ __half g_y1hi[NN * 128];    // aggregated layer1 hi
__device__ __half g_y1lo[NN * 128];
__device__ __half g_y2hi[NN * 256];    // aggregated layer2 hi
__device__ __half g_y2lo[NN * 256];
__device__ float  g_out1[NN * 128];
__device__ float  g_out2[NN * 256];
__device__ float  g_as1[NN * 2];
__device__ float  g_ad1[NN * 2];
__device__ float  g_as2[NN * 2];
__device__ float  g_ad2[NN * 2];
__device__ float  g_part[GB2 * 2 * 256];
__device__ float  g_scale[256];
__device__ float  g_shift[256];
__device__ float4 g_u1[64];
__device__ float4 g_u2[128];

// ------------------------------ helpers -------------------------------------
__device__ __forceinline__ void split16(float v, __half& h, __half& l) {
    h = __float2half_rn(v);
    l = __float2half_rn(v - __half2float(h));
}
__device__ __forceinline__ int edge_val(const void* ei, int idx, int is64) {
    if (is64) return (int)((const long long*)ei)[idx];
    return ((const int*)ei)[idx];
}
__device__ __forceinline__ void mma16816(
    float* c, const unsigned* a, const unsigned* b)
{
    asm volatile(
        "mma.sync.aligned.m16n8k16.row.col.f32.f16.f16.f32 "
        "{%0,%1,%2,%3}, {%4,%5,%6,%7}, {%8,%9}, {%0,%1,%2,%3};"
        : "+f"(c[0]), "+f"(c[1]), "+f"(c[2]), "+f"(c[3])
        : "r"(a[0]), "r"(a[1]), "r"(a[2]), "r"(a[3]), "r"(b[0]), "r"(b[1]));
}

// -------- prep: hist (per-block is64) + attvec + W2/W1 split-fp16 -----------
__global__ __launch_bounds__(256) void prep_kernel(
    const void* __restrict__ ei,
    const float* __restrict__ W1, const float* __restrict__ s1,
    const float* __restrict__ d1,
    const float* __restrict__ W2, const float* __restrict__ s2,
    const float* __restrict__ d2)
{
    const int bx = blockIdx.x;
    const int tid = threadIdx.x;
    if (bx < HB) {
        const int* ei32 = (const int*)ei;
        __shared__ int s_is64;
        if (tid < 32) {
            int a = ei32[2 * tid + 1];
            int b = ei32[2 * (tid + 32) + 1];
            unsigned m = __ballot_sync(0xffffffffu, (a | b) != 0);
            if (tid == 0) {
                s_is64 = (m == 0) ? 1 : 0;
                if (bx == 0) g_is64 = s_is64;
            }
        }
        __syncthreads();
        const int is64 = s_is64;
        int e = bx * 256 + tid;
        int dst = edge_val(ei, EE + e, is64);
        g_rank[e] = atomicAdd(&g_deg[dst], 1);
        return;
    }
    if (bx < HB + 24) {    // attention vectors
        const int lane = tid & 31;
        const int f = (bx - HB) * 8 + (tid >> 5);   // 0..191
        float4 u = make_float4(0.f, 0.f, 0.f, 0.f);
        if (f < 64) {
            #pragma unroll
            for (int c = lane; c < 64; c += 32) {
                float w0 = W1[f * 128 + c], w1 = W1[f * 128 + 64 + c];
                u.x += w0 * s1[c];      u.y += w1 * s1[64 + c];
                u.z += w0 * d1[c];      u.w += w1 * d1[64 + c];
            }
        } else {
            int f2 = f - 64;
            #pragma unroll
            for (int c = lane; c < 128; c += 32) {
                float w0 = W2[f2 * 256 + c], w1 = W2[f2 * 256 + 128 + c];
                u.x += w0 * s2[c];      u.y += w1 * s2[128 + c];
                u.z += w0 * d2[c];      u.w += w1 * d2[128 + c];
            }
        }
        #pragma unroll
        for (int o = 16; o; o >>= 1) {
            u.x += __shfl_xor_sync(0xffffffffu, u.x, o);
            u.y += __shfl_xor_sync(0xffffffffu, u.y, o);
            u.z += __shfl_xor_sync(0xffffffffu, u.z, o);
            u.w += __shfl_xor_sync(0xffffffffu, u.w, o);
        }
        if (lane == 0) {
            if (f < 64) g_u1[f] = u;
            else        g_u2[f - 64] = u;
        }
        return;
    }
    if (bx < HB + 56) {   // W2^T split: 32 blocks
        int t4 = (bx - HB - 24) * 256 + tid;
        int e = t4 * 4;
        int k = e >> 8;
        int n0 = e & 255;
        float4 w = *(const float4*)&W2[k * 256 + n0];
        __half h, l;
        split16(w.x, h, l); g_w2hi[(n0 + 0) * 128 + k] = h; g_w2lo[(n0 + 0) * 128 + k] = l;
        split16(w.y, h, l); g_w2hi[(n0 + 1) * 128 + k] = h; g_w2lo[(n0 + 1) * 128 + k] = l;
        split16(w.z, h, l); g_w2hi[(n0 + 2) * 128 + k] = h; g_w2lo[(n0 + 2) * 128 + k] = l;
        split16(w.w, h, l); g_w2hi[(n0 + 3) * 128 + k] = h; g_w2lo[(n0 + 3) * 128 + k] = l;
        return;
    }
    {   // W1^T split: 8 blocks
        int t4 = (bx - HB - 56) * 256 + tid;
        int e = t4 * 4;
        int k = e >> 7;
        int n0 = e & 127;
        float4 w = *(const float4*)&W1[k * 128 + n0];
        __half h, l;
        split16(w.x, h, l); g_w1hi[(n0 + 0) * 64 + k] = h; g_w1lo[(n0 + 0) * 64 + k] = l;
        split16(w.y, h, l); g_w1hi[(n0 + 1) * 64 + k] = h; g_w1lo[(n0 + 1) * 64 + k] = l;
        split16(w.z, h, l); g_w1hi[(n0 + 2) * 64 + k] = h; g_w1lo[(n0 + 2) * 64 + k] = l;
        split16(w.w, h, l); g_w1hi[(n0 + 3) * 64 + k] = h; g_w1lo[(n0 + 3) * 64 + k] = l;
    }
}

// ----------------- rowptr: scan + spin + deg reset for next replay ----------
__global__ __launch_bounds__(256) void rowptr_kernel() {
    __shared__ int s[256];
    const int t = threadIdx.x;
    const int bx = blockIdx.x;
    const int i = bx * 256 + t;
    int d = (i < NN) ? g_deg[i] : 0;
    if (i < NN) g_deg[i] = 0;
    s[t] = d;
    __syncthreads();
    for (int o = 1; o < 256; o <<= 1) {
        int u = (t >= o) ? s[t - o] : 0;
        __syncthreads();
        s[t] += u;
        __syncthreads();
    }
    const int incl = s[t];
    if (t == 255) {
        g_bsum[bx] = incl;
        __threadfence();
        atomicAdd(&g_ready, 1);
        while (atomicAdd(&g_ready, 0) < (int)gridDim.x) {}
    }
    __syncthreads();
    int pre = 0;
    for (int b = t; b < bx; b += 256) pre += g_bsum[b];
    #pragma unroll
    for (int o = 16; o; o >>= 1) pre += __shfl_xor_sync(0xffffffffu, pre, o);
    __shared__ int ws[8];
    if ((t & 31) == 0) ws[t >> 5] = pre;
    __syncthreads();
    if (t == 0) {
        int p = 0;
        #pragma unroll
        for (int w = 0; w < 8; w++) p += ws[w];
        s[0] = p;
    }
    __syncthreads();
    const int bpre = s[0];
    if (i < NN) g_rowptr[i] = bpre + incl - d;
    if (i == NN - 1) g_rowptr[NN] = bpre + incl;
    if (t == 0 && atomicAdd(&g_done, 1) == (int)gridDim.x - 1) {
        g_ready = 0;
        g_done = 0;
    }
}

// --------------------------- score GEMV body --------------------------------
template <int K, bool BN>
__device__ __forceinline__ void gemv_body(
    int node, const float* __restrict__ A, const float4* __restrict__ U,
    float* __restrict__ as_out, float* __restrict__ ad_out,
    __half* __restrict__ h16, int lane)
{
    float4 acc = make_float4(0.f, 0.f, 0.f, 0.f);
    #pragma unroll
    for (int f = lane; f < K; f += 32) {
        float v = A[(size_t)node * K + f];
        if (BN) {
            v = v * g_scale[f] + g_shift[f];
            v = v > 0.f ? v : 0.f;
            h16[(size_t)node * K + f] = __float2half_rn(v);
        }
        float4 u = U[f];
        acc.x += v * u.x; acc.y += v * u.y;
        acc.z += v * u.z; acc.w += v * u.w;
    }
    #pragma unroll
    for (int o = 16; o; o >>= 1) {
        acc.x += __shfl_xor_sync(0xffffffffu, acc.x, o);
        acc.y += __shfl_xor_sync(0xffffffffu, acc.y, o);
        acc.z += __shfl_xor_sync(0xffffffffu, acc.z, o);
        acc.w += __shfl_xor_sync(0xffffffffu, acc.w, o);
    }
    if (lane == 0) {
        as_out[node * 2 + 0] = acc.x;
        as_out[node * 2 + 1] = acc.y;
        ad_out[node * 2 + 0] = acc.z;
        ad_out[node * 2 + 1] = acc.w;
    }
}

__global__ __launch_bounds__(256) void scatter_gemv1_kernel(
    const void* __restrict__ ei, const float* __restrict__ x,
    const float4* __restrict__ U,
    float* __restrict__ as_out, float* __restrict__ ad_out)
{
    const int bx = blockIdx.x;
    if (bx < HB) {
        int e = bx * 256 + threadIdx.x;
        int is64 = g_is64;
        int src = edge_val(ei, e, is64);
        int dst = edge_val(ei, EE + e, is64);
        g_col[g_rowptr[dst] + g_rank[e]] = src;
        return;
    }
    const int node = (bx - HB) * 8 + (threadIdx.x >> 5);
    gemv_body<64, false>(node, x, U, as_out, ad_out, nullptr,
                         threadIdx.x & 31);
}

__global__ __launch_bounds__(256) void gemv2_kernel(
    const float* __restrict__ A, const float4* __restrict__ U,
    float* __restrict__ as_out, float* __restrict__ ad_out,
    __half* __restrict__ h16)
{
    const int node = blockIdx.x * 8 + (threadIdx.x >> 5);
    gemv_body<128, true>(node, A, U, as_out, ad_out, h16, threadIdx.x & 31);
}

// ------------------- segment softmax + weighted aggregate ------------------
// Batched-32 edges per warp. HALF_SRC: fp16 rows (layer 2) vs fp32 (layer 1).
template <int F, bool HALF_SRC>
__global__ __launch_bounds__(256) void agg_kernel(
    const void* __restrict__ srcv, const float* __restrict__ as,
    const float* __restrict__ ad,
    __half* __restrict__ yhi, __half* __restrict__ ylo)
{
    const int lane = threadIdx.x & 31;
    const int warp = threadIdx.x >> 5;
    const int node = blockIdx.x * 8 + warp;
    constexpr int V = F / 32;   // elems per lane: 2 or 4
    using RowT = typename std::conditional<
        HALF_SRC, typename std::conditional<V == 2, unsigned, uint2>::type,
                  typename std::conditional<V == 2, float2, float4>::type>::type;
    const int base = g_rowptr[node];
    const int deg = g_rowptr[node + 1] - base;
    const float2* as2 = (const float2*)as;
    const float2 adi = ((const float2*)ad)[node];

    float acc0[V], acc1[V];
    #pragma unroll
    for (int v = 0; v < V; v++) { acc0[v] = 0.f; acc1[v] = 0.f; }
    float zp0 = 0.f, zp1 = 0.f;

    auto row_ptr = [&](int s) -> const RowT* {
        if constexpr (HALF_SRC)
            return (const RowT*)((const __half*)srcv + (size_t)s * F + lane * V);
        else
            return (const RowT*)((const float*)srcv + (size_t)s * F + lane * V);
    };

    auto accum = [&](RowT u, float p0, float p1) {
        if constexpr (HALF_SRC) {
            if constexpr (V == 2) {
                float2 f = __half22float2(*(__half2*)&u);
                acc0[0] += p0 * f.x; acc0[1] += p0 * f.y;
                acc1[0] += p1 * f.x; acc1[1] += p1 * f.y;
            } else {
                float2 f0 = __half22float2(*(__half2*)&u.x);
                float2 f1 = __half22float2(*(__half2*)&u.y);
                acc0[0] += p0 * f0.x; acc0[1] += p0 * f0.y;
                acc0[2] += p0 * f1.x; acc0[3] += p0 * f1.y;
                acc1[0] += p1 * f0.x; acc1[1] += p1 * f0.y;
                acc1[2] += p1 * f1.x; acc1[3] += p1 * f1.y;
            }
        } else {
            if constexpr (V == 2) {
                acc0[0] += p0 * u.x; acc0[1] += p0 * u.y;
                acc1[0] += p1 * u.x; acc1[1] += p1 * u.y;
            } else {
                acc0[0] += p0 * u.x; acc0[1] += p0 * u.y;
                acc0[2] += p0 * u.z; acc0[3] += p0 * u.w;
                acc1[0] += p1 * u.x; acc1[1] += p1 * u.y;
                acc1[2] += p1 * u.z; acc1[3] += p1 * u.w;
            }
        }
    };

    {   // self loop
        float2 a = as2[node];
        float e0 = a.x + adi.x; e0 = e0 > 0.f ? e0 : 0.2f * e0;
        float e1 = a.y + adi.y; e1 = e1 > 0.f ? e1 : 0.2f * e1;
        float p0 = __expf(e0), p1 = __expf(e1);
        if (lane == 0) { zp0 += p0; zp1 += p1; }
        accum(*row_ptr(node), p0, p1);
    }

    for (int j0 = 0; j0 < deg; j0 += 32) {
        const int nb = min(32, deg - j0);
        int sl = 0; float p0 = 0.f, p1 = 0.f;
        if (lane < nb) {
            sl = g_col[base + j0 + lane];
            float2 a = as2[sl];
            float e0 = a.x + adi.x; e0 = e0 > 0.f ? e0 : 0.2f * e0;
            float e1 = a.y + adi.y; e1 = e1 > 0.f ? e1 : 0.2f * e1;
            p0 = __expf(e0); p1 = __expf(e1);
        }
        zp0 += p0; zp1 += p1;
        if (nb == 32) {
            #pragma unroll 8
            for (int k = 0; k < 32; k++) {
                int sk = __shfl_sync(0xffffffffu, sl, k);
                float q0 = __shfl_sync(0xffffffffu, p0, k);
                float q1 = __shfl_sync(0xffffffffu, p1, k);
                accum(*row_ptr(sk), q0, q1);
            }
        } else {
            for (int k = 0; k < nb; k++) {
                int sk = __shfl_sync(0xffffffffu, sl, k);
                float q0 = __shfl_sync(0xffffffffu, p0, k);
                float q1 = __shfl_sync(0xffffffffu, p1, k);
                accum(*row_ptr(sk), q0, q1);
            }
        }
    }

    #pragma unroll
    for (int o = 16; o; o >>= 1) {
        zp0 += __shfl_xor_sync(0xffffffffu, zp0, o);
        zp1 += __shfl_xor_sync(0xffffffffu, zp1, o);
    }
    const float i0 = 1.f / zp0, i1 = 1.f / zp1;

    if constexpr (V == 2) {
        __half h0, l0, h1, l1, h2, l2, h3, l3;
        split16(acc0[0] * i0, h0, l0);
        split16(acc0[1] * i0, h1, l1);
        split16(acc1[0] * i1, h2, l2);
        split16(acc1[1] * i1, h3, l3);
        size_t off0 = (size_t)node * 2 * F + lane * 2;
        size_t off1 = off0 + F;
        *(__half2*)(yhi + off0) = __halves2half2(h0, h1);
        *(__half2*)(yhi + off1) = __halves2half2(h2, h3);
        *(__half2*)(ylo + off0) = __halves2half2(l0, l1);
        *(__half2*)(ylo + off1) = __halves2half2(l2, l3);
    } else {
        float v0[4], v1[4];
        #pragma unroll
        for (int v = 0; v < 4; v++) { v0[v] = acc0[v] * i0; v1[v] = acc1[v] * i1; }
        __half h[8], l[8];
        #pragma unroll
        for (int v = 0; v < 4; v++) split16(v0[v], h[v], l[v]);
        #pragma unroll
        for (int v = 0; v < 4; v++) split16(v1[v], h[4 + v], l[4 + v]);
        size_t off0 = (size_t)node * 2 * F + lane * 4;
        size_t off1 = off0 + F;
        *(uint2*)(yhi + off0) = *(uint2*)&h[0];
        *(uint2*)(yhi + off1) = *(uint2*)&h[4];
        *(uint2*)(ylo + off0) = *(uint2*)&l[0];
        *(uint2*)(ylo + off1) = *(uint2*)&l[4];
    }
}

// ------- shared MMA gemm: smem-staged split-fp16, + BN stats + finalize -----
template <int K, int LD, int NY, int PAD>
__global__ __launch_bounds__(256) void gemm_mma_kernel(
    const __half* __restrict__ Ahi, const __half* __restrict__ Alo,
    const __half* __restrict__ Whi, const __half* __restrict__ Wlo,
    const float* __restrict__ bias, const float* __restrict__ gamma,
    const float* __restrict__ beta, float* __restrict__ C)
{
    extern __shared__ __half sm[];
    __half* sAhi = sm;
    __half* sAlo = sm + 128 * PAD;
    __half* sBhi = sm + 2 * 128 * PAD;
    __half* sBlo = sBhi + 64 * PAD;
    __shared__ float s_s[64], s_q[64];

    const int tid = threadIdx.x;
    const int warp = tid >> 5, lane = tid & 31;
    const int mw = warp & 3;
    const int nw = warp >> 2;
    const int head = (NY == 2) ? (int)blockIdx.y : ((int)blockIdx.y >> 1);
    const int nb = (NY == 2) ? 0 : ((int)blockIdx.y & 1);
    const int row0b = blockIdx.x * 128;
    const int cbA = head * K;
    const int cbC = head * (LD / 2) + nb * 64;
    const int g = lane >> 2;
    const int tk = (lane & 3) * 2;
    if (tid < 64) { s_s[tid] = 0.f; s_q[tid] = 0.f; }

    constexpr int AU = 128 * K / 8;
    #pragma unroll
    for (int i = tid; i < AU; i += 256) {
        int r = i / (K / 8);
        int c8 = (i % (K / 8)) * 8;
        int gr = row0b + r;
        uint4 vh = make_uint4(0u, 0u, 0u, 0u);
        uint4 vl = vh;
        if (gr < NN) {
            vh = *(const uint4*)(Ahi + (size_t)gr * LD + cbA + c8);
            vl = *(const uint4*)(Alo + (size_t)gr * LD + cbA + c8);
        }
        *(uint4*)(sAhi + r * PAD + c8) = vh;
        *(uint4*)(sAlo + r * PAD + c8) = vl;
    }
    constexpr int BU = 64 * K / 8;
    #pragma unroll
    for (int i = tid; i < BU; i += 256) {
        int n = i / (K / 8);
        int c8 = (i % (K / 8)) * 8;
        uint4 vh = *(const uint4*)(Whi + (size_t)(cbC + n) * K + c8);
        uint4 vl = *(const uint4*)(Wlo + (size_t)(cbC + n) * K + c8);
        *(uint4*)(sBhi + n * PAD + c8) = vh;
        *(uint4*)(sBlo + n * PAD + c8) = vl;
    }
    __syncthreads();

    float acc[2][4][4];
    #pragma unroll
    for (int mi = 0; mi < 2; mi++)
        #pragma unroll
        for (int ni = 0; ni < 4; ni++)
            #pragma unroll
            for (int j = 0; j < 4; j++) acc[mi][ni][j] = 0.f;

    #pragma unroll 1
    for (int k0 = 0; k0 < K; k0 += 16) {
        unsigned ah[2][4], al[2][4];
        #pragma unroll
        for (int mi = 0; mi < 2; mi++) {
            int row = mw * 32 + mi * 16 + g;
            const __half* p = sAhi + row * PAD + k0 + tk;
            const __half* q = sAlo + row * PAD + k0 + tk;
            ah[mi][0] = *(const unsigned*)p;
            ah[mi][1] = *(const unsigned*)(p + 8 * PAD);
            ah[mi][2] = *(const unsigned*)(p + 8);
            ah[mi][3] = *(const unsigned*)(p + 8 * PAD + 8);
            al[mi][0] = *(const unsigned*)q;
            al[mi][1] = *(const unsigned*)(q + 8 * PAD);
            al[mi][2] = *(const unsigned*)(q + 8);
            al[mi][3] = *(const unsigned*)(q + 8 * PAD + 8);
        }
        unsigned bh[4][2], bl[4][2];
        #pragma unroll
        for (int ni = 0; ni < 4; ni++) {
            int n = nw * 32 + ni * 8 + g;
            const __half* p = sBhi + n * PAD + k0 + tk;
            const __half* q = sBlo + n * PAD + k0 + tk;
            bh[ni][0] = *(const unsigned*)p;
            bh[ni][1] = *(const unsigned*)(p + 8);
            bl[ni][0] = *(const unsigned*)q;
            bl[ni][1] = *(const unsigned*)(q + 8);
        }
        #pragma unroll
        for (int mi = 0; mi < 2; mi++)
            #pragma unroll
            for (int ni = 0; ni < 4; ni++) {
                mma16816(acc[mi][ni], ah[mi], bh[ni]);
                mma16816(acc[mi][ni], al[mi], bh[ni]);
                mma16816(acc[mi][ni], ah[mi], bl[ni]);
            }
    }
    __syncthreads();
    const int nbase = cbC + nw * 32;
    #pragma unroll
    for (int ni = 0; ni < 4; ni++) {
        const int col = nbase + ni * 8 + tk;
        float2 bv = *(const float2*)&bias[col];
        float s0 = 0.f, s1 = 0.f, q0 = 0.f, q1 = 0.f;
        #pragma unroll
        for (int mi = 0; mi < 2; mi++) {
            int r0 = row0b + mw * 32 + mi * 16 + g;
            int r1 = r0 + 8;
            float c0 = acc[mi][ni][0] + bv.x;
            float c1 = acc[mi][ni][1] + bv.y;
            float c2 = acc[mi][ni][2] + bv.x;
            float c3 = acc[mi][ni][3] + bv.y;
            if (r0 < NN) {
                *(float2*)&C[(size_t)r0 * LD + col] = make_float2(c0, c1);
                s0 += c0; s1 += c1; q0 += c0 * c0; q1 += c1 * c1;
            }
            if (r1 < NN) {
                *(float2*)&C[(size_t)r1 * LD + col] = make_float2(c2, c3);
                s0 += c2; s1 += c3; q0 += c2 * c2; q1 += c3 * c3;
            }
        }
        #pragma unroll
        for (int o = 4; o < 32; o <<= 1) {
            s0 += __shfl_xor_sync(0xffffffffu, s0, o);
            s1 += __shfl_xor_sync(0xffffffffu, s1, o);
            q0 += __shfl_xor_sync(0xffffffffu, q0, o);
            q1 += __shfl_xor_sync(0xffffffffu, q1, o);
        }
        if (g == 0) {
            int cl = nw * 32 + ni * 8 + tk;
            atomicAdd(&s_s[cl], s0);     atomicAdd(&s_s[cl + 1], s1);
            atomicAdd(&s_q[cl], q0);     atomicAdd(&s_q[cl + 1], q1);
        }
    }
    __syncthreads();
    if (tid < 64) {
        g_part[blockIdx.x * 2 * LD + cbC + tid] = s_s[tid];
        g_part[blockIdx.x * 2 * LD + LD + cbC + tid] = s_q[tid];
    }
    __shared__ int last;
    __threadfence();
    __syncthreads();
    if (tid == 0)
        last = (atomicAdd(&g_tick, 1) == (int)(gridDim.x * gridDim.y) - 1);
    __syncthreads();
    if (!last) return;
    for (int col = tid; col < LD; col += 256) {
        float s = 0.f, q = 0.f;
        for (int b = 0; b < GB2; b++) {
            s += g_part[b * 2 * LD + col];
            q += g_part[b * 2 * LD + LD + col];
        }
        const float mu = s * (1.f / NN);
        const float var = q * (1.f / NN) - mu * mu;
        const float sc = gamma[col] * rsqrtf(var + 1e-5f);
        g_scale[col] = sc;
        g_shift[col] = beta[col] - mu * sc;
    }
    if (tid == 0) g_tick = 0;
}

__global__ void bnapply_kernel(const float4* __restrict__ X,
                               float4* __restrict__ Y, int total4) {
    int i = blockIdx.x * blockDim.x + threadIdx.x;
    if (i >= total4) return;
    int c = (i & 63) * 4;
    float4 v = X[i];
    float4 sc = *(const float4*)&g_scale[c];
    float4 sh = *(const float4*)&g_shift[c];
    v.x = fmaxf(v.x * sc.x + sh.x, 0.f);
    v.y = fmaxf(v.y * sc.y + sh.y, 0.f);
    v.z = fmaxf(v.z * sc.z + sh.z, 0.f);
    v.w = fmaxf(v.w * sc.w + sh.w, 0.f);
    Y[i] = v;
}

// ------------------------------- launcher -----------------------------------
extern "C" void kernel_launch(void* const* d_in, const int* in_sizes, int n_in,
                              void* d_out, int out_size) {
    const float* x        = (const float*)d_in[0];
    const void*  ei       = d_in[1];
    const float* W1       = (const float*)d_in[2];
    const float* att_src1 = (const float*)d_in[3];
    const float* att_dst1 = (const float*)d_in[4];
    const float* bias1    = (const float*)d_in[5];
    const float* gamma1   = (const float*)d_in[6];
    const float* beta1    = (const float*)d_in[7];
    const float* W2       = (const float*)d_in[8];
    const float* att_src2 = (const float*)d_in[9];
    const float* att_dst2 = (const float*)d_in[10];
    const float* bias2    = (const float*)d_in[11];
    const float* gamma2   = (const float*)d_in[12];
    const float* beta2    = (const float*)d_in[13];
    float* out = (float*)d_out;

    __half *h16, *y1hi, *y1lo, *y2hi, *y2lo, *w1hi, *w1lo, *w2hi, *w2lo;
    float *out1, *out2, *as1, *ad1, *as2, *ad2;
    float4 *u1, *u2;
    cudaGetSymbolAddress((void**)&h16,  g_h16);
    cudaGetSymbolAddress((void**)&y1hi, g_y1hi);
    cudaGetSymbolAddress((void**)&y1lo, g_y1lo);
    cudaGetSymbolAddress((void**)&y2hi, g_y2hi);
    cudaGetSymbolAddress((void**)&y2lo, g_y2lo);
    cudaGetSymbolAddress((void**)&w1hi, g_w1hi);
    cudaGetSymbolAddress((void**)&w1lo, g_w1lo);
    cudaGetSymbolAddress((void**)&w2hi, g_w2hi);
    cudaGetSymbolAddress((void**)&w2lo, g_w2lo);
    cudaGetSymbolAddress((void**)&out1, g_out1);
    cudaGetSymbolAddress((void**)&out2, g_out2);
    cudaGetSymbolAddress((void**)&as1,  g_as1);
    cudaGetSymbolAddress((void**)&ad1,  g_ad1);
    cudaGetSymbolAddress((void**)&as2,  g_as2);
    cudaGetSymbolAddress((void**)&ad2,  g_ad2);
    cudaGetSymbolAddress((void**)&u1,   g_u1);
    cudaGetSymbolAddress((void**)&u2,   g_u2);

    cudaFuncSetAttribute((const void*)gemm_mma_kernel<64, 128, 2, PAD1>,
                         cudaFuncAttributeMaxDynamicSharedMemorySize,
                         SM1_BYTES);
    cudaFuncSetAttribute((const void*)gemm_mma_kernel<128, 256, 4, PAD2>,
                         cudaFuncAttributeMaxDynamicSharedMemorySize,
                         SM2_BYTES);

    prep_kernel<<<HB + 64, 256>>>(ei, W1, att_src1, att_dst1,
                                  W2, att_src2, att_dst2);
    rowptr_kernel<<<CB, 256>>>();
    scatter_gemv1_kernel<<<HB + NN / 8, 256>>>(ei, x, u1, as1, ad1);

    agg_kernel<64, false><<<NN / 8, 256>>>(x, as1, ad1, y1hi, y1lo);
    gemm_mma_kernel<64, 128, 2, PAD1><<<dim3(GB2, 2), 256, SM1_BYTES>>>(
        y1hi, y1lo, w1hi, w1lo, bias1, gamma1, beta1, out1);
    gemv2_kernel<<<NN / 8, 256>>>(out1, u2, as2, ad2, h16);
    agg_kernel<128, true><<<NN / 8, 256>>>(h16, as2, ad2, y2hi, y2lo);
    gemm_mma_kernel<128, 256, 4, PAD2><<<dim3(GB2, 4), 256, SM2_BYTES>>>(
        y2hi, y2lo, w2hi, w2lo, bias2, gamma2, beta2, out2);
    bnapply_kernel<<<(NN * 64 + 255) / 256, 256>>>((const float4*)out2,
                                                   (float4*)out, NN * 64);
}